// round 3
// baseline (speedup 1.0000x reference)
#include <cuda_runtime.h>
#include <cuda_bf16.h>
#include <cstdint>
#include <math.h>

typedef __nv_bfloat16 bf16;

#define NN 4096
#define CC 512
#define LL 64

// ---------------- scratch (device globals: no allocations allowed) ----------
__device__ bf16  g_adjb[(size_t)NN * NN];     // 32 MB  adj in bf16
__device__ bf16  g_Xhi[NN * CC];
__device__ bf16  g_Xlo[NN * CC];
__device__ bf16  g_Wfhi[CC * CC];
__device__ bf16  g_Wflo[CC * CC];
__device__ bf16  g_Wprojb[CC * LL];
__device__ bf16  g_Wpi1b[LL * CC];
__device__ bf16  g_Zb[NN * LL];
__device__ bf16  g_Hb[NN * CC];
__device__ bf16  g_stb[NN * CC];              // v[row] * target, bf16
__device__ float g_target[NN * CC];           // fp32 target
__device__ float g_q[NN];
__device__ float g_v[NN];
__device__ float g_d[NN];

// ---------------- PTX helpers ----------------------------------------------
__device__ __forceinline__ uint32_t smem_u32(const void* p) {
    return (uint32_t)__cvta_generic_to_shared(p);
}
__device__ __forceinline__ void cp_async16(uint32_t s, const void* g) {
    asm volatile("cp.async.cg.shared.global [%0], [%1], 16;\n" :: "r"(s), "l"(g) : "memory");
}
__device__ __forceinline__ void cp_commit() {
    asm volatile("cp.async.commit_group;\n" ::: "memory");
}
__device__ __forceinline__ void cp_wait0() {
    asm volatile("cp.async.wait_group 0;\n" ::: "memory");
}
__device__ __forceinline__ void ldsm_x4(uint32_t* r, uint32_t a) {
    asm volatile("ldmatrix.sync.aligned.m8n8.x4.shared.b16 {%0,%1,%2,%3}, [%4];"
                 : "=r"(r[0]), "=r"(r[1]), "=r"(r[2]), "=r"(r[3]) : "r"(a));
}
__device__ __forceinline__ void ldsm_x2t(uint32_t* r, uint32_t a) {
    asm volatile("ldmatrix.sync.aligned.m8n8.x2.trans.shared.b16 {%0,%1}, [%2];"
                 : "=r"(r[0]), "=r"(r[1]) : "r"(a));
}
__device__ __forceinline__ void mma_bf16(float* c, const uint32_t* a, const uint32_t* b) {
    asm volatile("mma.sync.aligned.m16n8k16.row.col.f32.bf16.bf16.f32 "
                 "{%0,%1,%2,%3}, {%4,%5,%6,%7}, {%8,%9}, {%0,%1,%2,%3};"
                 : "+f"(c[0]), "+f"(c[1]), "+f"(c[2]), "+f"(c[3])
                 : "r"(a[0]), "r"(a[1]), "r"(a[2]), "r"(a[3]), "r"(b[0]), "r"(b[1]));
}

// ---------------- small conversion kernels ----------------------------------
__global__ void k_f2b(const float* __restrict__ s, bf16* __restrict__ d, int n) {
    int i = blockIdx.x * blockDim.x + threadIdx.x;
    if (i < n) d[i] = __float2bfloat16(s[i]);
}
__global__ void k_split(const float* __restrict__ s, bf16* __restrict__ hi,
                        bf16* __restrict__ lo, int n) {
    int i = blockIdx.x * blockDim.x + threadIdx.x;
    if (i < n) {
        float f = s[i];
        bf16 h = __float2bfloat16(f);
        hi[i] = h;
        lo[i] = __float2bfloat16(f - __bfloat162float(h));
    }
}

// q[i] = sum_j adj[i,j]  (fp32), and convert adj -> bf16
__global__ void k_rowsum_convert(const float* __restrict__ adj,
                                 bf16* __restrict__ adjb, float* __restrict__ q) {
    int row = blockIdx.x, t = threadIdx.x;  // 256 threads
    const float4* src = reinterpret_cast<const float4*>(adj + (size_t)row * NN);
    uint2* dst = reinterpret_cast<uint2*>(adjb + (size_t)row * NN);
    float s = 0.f;
#pragma unroll
    for (int i = 0; i < 4; i++) {
        float4 f = src[t + i * 256];
        s += (f.x + f.y) + (f.z + f.w);
        __nv_bfloat162 b0 = __floats2bfloat162_rn(f.x, f.y);
        __nv_bfloat162 b1 = __floats2bfloat162_rn(f.z, f.w);
        uint2 u;
        u.x = *reinterpret_cast<uint32_t*>(&b0);
        u.y = *reinterpret_cast<uint32_t*>(&b1);
        dst[t + i * 256] = u;
    }
    for (int o = 16; o > 0; o >>= 1) s += __shfl_xor_sync(0xffffffffu, s, o);
    __shared__ float ws[8];
    if ((t & 31) == 0) ws[t >> 5] = s;
    __syncthreads();
    if (t == 0) {
        float tot = 0.f;
#pragma unroll
        for (int i = 0; i < 8; i++) tot += ws[i];
        q[row] = tot;
    }
}

// pi per row: sigmoid(H[row,:] . W_pi2 + b_pi2); v = pi / q
__global__ void k_pi(const bf16* __restrict__ H, const float* __restrict__ W2,
                     const float* __restrict__ b2, const float* __restrict__ q,
                     float* __restrict__ v) {
    int row = blockIdx.x, t = threadIdx.x;  // 128 threads
    uint2 u = reinterpret_cast<const uint2*>(H + (size_t)row * CC)[t];
    float4 w = reinterpret_cast<const float4*>(W2)[t];
    __nv_bfloat162 p0 = *reinterpret_cast<__nv_bfloat162*>(&u.x);
    __nv_bfloat162 p1 = *reinterpret_cast<__nv_bfloat162*>(&u.y);
    float s = __bfloat162float(p0.x) * w.x + __bfloat162float(p0.y) * w.y +
              __bfloat162float(p1.x) * w.z + __bfloat162float(p1.y) * w.w;
    for (int o = 16; o > 0; o >>= 1) s += __shfl_xor_sync(0xffffffffu, s, o);
    __shared__ float ws[4];
    if ((t & 31) == 0) ws[t >> 5] = s;
    __syncthreads();
    if (t == 0) {
        s = ws[0] + ws[1] + ws[2] + ws[3] + b2[0];
        float pi = 1.f / (1.f + expf(-s));
        v[row] = pi / q[row];
    }
}

// d[i] = sum_j adjb[i,j] * v[j] + 1e-5
__global__ void k_dvec(const bf16* __restrict__ adjb, const float* __restrict__ v,
                       float* __restrict__ d) {
    int row = blockIdx.x, t = threadIdx.x;  // 256 threads
    const uint4* ap = reinterpret_cast<const uint4*>(adjb + (size_t)row * NN);
    float s = 0.f;
#pragma unroll
    for (int i = 0; i < 2; i++) {
        int ci = t + i * 256;  // chunk of 8 bf16
        uint4 u = ap[ci];
        const float4* vp = reinterpret_cast<const float4*>(v + ci * 8);
        float4 v0 = vp[0], v1 = vp[1];
        __nv_bfloat162 a0 = *reinterpret_cast<__nv_bfloat162*>(&u.x);
        __nv_bfloat162 a1 = *reinterpret_cast<__nv_bfloat162*>(&u.y);
        __nv_bfloat162 a2 = *reinterpret_cast<__nv_bfloat162*>(&u.z);
        __nv_bfloat162 a3 = *reinterpret_cast<__nv_bfloat162*>(&u.w);
        s += __bfloat162float(a0.x) * v0.x + __bfloat162float(a0.y) * v0.y +
             __bfloat162float(a1.x) * v0.z + __bfloat162float(a1.y) * v0.w +
             __bfloat162float(a2.x) * v1.x + __bfloat162float(a2.y) * v1.y +
             __bfloat162float(a3.x) * v1.z + __bfloat162float(a3.y) * v1.w;
    }
    for (int o = 16; o > 0; o >>= 1) s += __shfl_xor_sync(0xffffffffu, s, o);
    __shared__ float ws[8];
    if ((t & 31) == 0) ws[t >> 5] = s;
    __syncthreads();
    if (t == 0) {
        float tot = 0.f;
#pragma unroll
        for (int i = 0; i < 8; i++) tot += ws[i];
        d[row] = tot + 1e-5f;
    }
}

// ---------------- generic bf16 mma GEMM (2-stage cp.async pipeline) ----------
// EPI: 0 = +bias -> bf16      (Z)
//      1 = relu(+bias) -> bf16 (H)
//      3 = out = (1-dt)*target + (dt/(0.25*d[row]))*acc  (final)
template <int BM, int BN, int BK, int WMC, int WNC, int EPI>
__global__ void __launch_bounds__(256)
gemm_bf16(const bf16* __restrict__ A, const bf16* __restrict__ B,
          int M, int N, int K,
          const float* __restrict__ bias, const float* __restrict__ dvec,
          const float* __restrict__ tgt, const float* __restrict__ dtp,
          float* __restrict__ outf, bf16* __restrict__ outb) {
    constexpr int WARP_M = BM / WMC, WARP_N = BN / WNC;
    constexpr int FM = WARP_M / 16, FN = WARP_N / 8;
    constexpr int LDA = BK + 8, LDB = BN + 8;
    __shared__ __align__(16) bf16 As[2][BM * LDA];
    __shared__ __align__(16) bf16 Bs[2][BK * LDB];

    const int tid = threadIdx.x, lane = tid & 31, warp = tid >> 5;
    const int wm = warp / WNC, wn = warp % WNC;
    const int bm0 = blockIdx.x * BM, bn0 = blockIdx.y * BN;
    constexpr int ACH = BM * BK / 8, BCH = BK * BN / 8;
    constexpr int ACPR = BK / 8, BCPR = BN / 8;

    float acc[FM][FN][4];
#pragma unroll
    for (int i = 0; i < FM; i++)
#pragma unroll
        for (int j = 0; j < FN; j++)
#pragma unroll
            for (int k = 0; k < 4; k++) acc[i][j][k] = 0.f;

    auto load_tiles = [&](int kt, int buf) {
        for (int c = tid; c < ACH; c += 256) {
            int r = c / ACPR, co = (c % ACPR) * 8;
            cp_async16(smem_u32(&As[buf][r * LDA + co]),
                       A + (size_t)(bm0 + r) * K + (size_t)kt * BK + co);
        }
        for (int c = tid; c < BCH; c += 256) {
            int r = c / BCPR, co = (c % BCPR) * 8;
            cp_async16(smem_u32(&Bs[buf][r * LDB + co]),
                       B + (size_t)(kt * BK + r) * N + bn0 + co);
        }
    };

    const int KT = K / BK;
    load_tiles(0, 0);
    cp_commit();
    for (int it = 0; it < KT; ++it) {
        int buf = it & 1;
        cp_wait0();
        __syncthreads();
        if (it + 1 < KT) {
            load_tiles(it + 1, buf ^ 1);
            cp_commit();
        }
#pragma unroll
        for (int kk = 0; kk < BK / 16; ++kk) {
            uint32_t af[FM][4], bfr[FN][2];
#pragma unroll
            for (int i = 0; i < FM; i++) {
                int r = wm * WARP_M + i * 16 + (lane & 15);
                int cc = kk * 16 + ((lane >> 4) << 3);
                ldsm_x4(af[i], smem_u32(&As[buf][r * LDA + cc]));
            }
#pragma unroll
            for (int j = 0; j < FN; j++) {
                int r = kk * 16 + (lane & 15);
                int cc = wn * WARP_N + j * 8;
                ldsm_x2t(bfr[j], smem_u32(&Bs[buf][r * LDB + cc]));
            }
#pragma unroll
            for (int i = 0; i < FM; i++)
#pragma unroll
                for (int j = 0; j < FN; j++) mma_bf16(acc[i][j], af[i], bfr[j]);
        }
    }

    // epilogue
    float dt1 = 0.f, mdt = 0.f;
    if constexpr (EPI == 3) {
        dt1 = dtp[0];
        mdt = 1.f - dt1;
    }
#pragma unroll
    for (int i = 0; i < FM; i++) {
        int rbase = bm0 + wm * WARP_M + i * 16 + (lane >> 2);
#pragma unroll
        for (int h = 0; h < 2; h++) {
            int r = rbase + h * 8;
            float rs = 0.f;
            if constexpr (EPI == 3) rs = dt1 / (0.25f * dvec[r]);
#pragma unroll
            for (int j = 0; j < FN; j++) {
                int c = bn0 + wn * WARP_N + j * 8 + (lane & 3) * 2;
                float x0 = acc[i][j][h * 2 + 0], x1 = acc[i][j][h * 2 + 1];
                size_t idx = (size_t)r * N + c;
                if constexpr (EPI == 0) {
                    x0 += bias[c];
                    x1 += bias[c + 1];
                    *reinterpret_cast<__nv_bfloat162*>(outb + idx) =
                        __floats2bfloat162_rn(x0, x1);
                } else if constexpr (EPI == 1) {
                    x0 = fmaxf(x0 + bias[c], 0.f);
                    x1 = fmaxf(x1 + bias[c + 1], 0.f);
                    *reinterpret_cast<__nv_bfloat162*>(outb + idx) =
                        __floats2bfloat162_rn(x0, x1);
                } else {
                    float2 tg = *reinterpret_cast<const float2*>(tgt + idx);
                    float2 o;
                    o.x = mdt * tg.x + rs * x0;
                    o.y = mdt * tg.y + rs * x1;
                    *reinterpret_cast<float2*>(outf + idx) = o;
                }
            }
        }
    }
}

// ---------------- split-bf16 (hi/lo) GEMM for target: fp32-accurate ---------
// acc = Ah*Bh + Ah*Bl + Al*Bh ; epilogue: target fp32 + st = v[row]*target bf16
template <int BM, int BN, int BK, int WMC, int WNC>
__global__ void __launch_bounds__(256)
gemm_split3(const bf16* __restrict__ Ah, const bf16* __restrict__ Al,
            const bf16* __restrict__ Bh, const bf16* __restrict__ Bl,
            int M, int N, int K,
            const float* __restrict__ bias, const float* __restrict__ vvec,
            float* __restrict__ outf, bf16* __restrict__ outb) {
    constexpr int WARP_M = BM / WMC, WARP_N = BN / WNC;
    constexpr int FM = WARP_M / 16, FN = WARP_N / 8;
    constexpr int LDA = BK + 8, LDB = BN + 8;
    __shared__ __align__(16) bf16 As[2][BM * LDA];  // [0]=hi [1]=lo
    __shared__ __align__(16) bf16 Bs[2][BK * LDB];

    const int tid = threadIdx.x, lane = tid & 31, warp = tid >> 5;
    const int wm = warp / WNC, wn = warp % WNC;
    const int bm0 = blockIdx.x * BM, bn0 = blockIdx.y * BN;
    constexpr int ACH = BM * BK / 8, BCH = BK * BN / 8;
    constexpr int ACPR = BK / 8, BCPR = BN / 8;

    float acc[FM][FN][4];
#pragma unroll
    for (int i = 0; i < FM; i++)
#pragma unroll
        for (int j = 0; j < FN; j++)
#pragma unroll
            for (int k = 0; k < 4; k++) acc[i][j][k] = 0.f;

    const int KT = K / BK;
    for (int it = 0; it < KT; ++it) {
        if (it > 0) __syncthreads();
        for (int c = tid; c < ACH; c += 256) {
            int r = c / ACPR, co = (c % ACPR) * 8;
            size_t g = (size_t)(bm0 + r) * K + (size_t)it * BK + co;
            cp_async16(smem_u32(&As[0][r * LDA + co]), Ah + g);
            cp_async16(smem_u32(&As[1][r * LDA + co]), Al + g);
        }
        for (int c = tid; c < BCH; c += 256) {
            int r = c / BCPR, co = (c % BCPR) * 8;
            size_t g = (size_t)(it * BK + r) * N + bn0 + co;
            cp_async16(smem_u32(&Bs[0][r * LDB + co]), Bh + g);
            cp_async16(smem_u32(&Bs[1][r * LDB + co]), Bl + g);
        }
        cp_commit();
        cp_wait0();
        __syncthreads();
#pragma unroll
        for (int kk = 0; kk < BK / 16; ++kk) {
            uint32_t ah[FM][4], al[FM][4], bh[FN][2], bl[FN][2];
#pragma unroll
            for (int i = 0; i < FM; i++) {
                int r = wm * WARP_M + i * 16 + (lane & 15);
                int cc = kk * 16 + ((lane >> 4) << 3);
                ldsm_x4(ah[i], smem_u32(&As[0][r * LDA + cc]));
                ldsm_x4(al[i], smem_u32(&As[1][r * LDA + cc]));
            }
#pragma unroll
            for (int j = 0; j < FN; j++) {
                int r = kk * 16 + (lane & 15);
                int cc = wn * WARP_N + j * 8;
                ldsm_x2t(bh[j], smem_u32(&Bs[0][r * LDB + cc]));
                ldsm_x2t(bl[j], smem_u32(&Bs[1][r * LDB + cc]));
            }
#pragma unroll
            for (int i = 0; i < FM; i++)
#pragma unroll
                for (int j = 0; j < FN; j++) {
                    mma_bf16(acc[i][j], ah[i], bh[j]);
                    mma_bf16(acc[i][j], ah[i], bl[j]);
                    mma_bf16(acc[i][j], al[i], bh[j]);
                }
        }
    }

#pragma unroll
    for (int i = 0; i < FM; i++) {
        int rbase = bm0 + wm * WARP_M + i * 16 + (lane >> 2);
#pragma unroll
        for (int h = 0; h < 2; h++) {
            int r = rbase + h * 8;
            float vr = vvec[r];
#pragma unroll
            for (int j = 0; j < FN; j++) {
                int c = bn0 + wn * WARP_N + j * 8 + (lane & 3) * 2;
                float x0 = fmaxf(acc[i][j][h * 2 + 0] + bias[c], 0.f);
                float x1 = fmaxf(acc[i][j][h * 2 + 1] + bias[c + 1], 0.f);
                size_t idx = (size_t)r * N + c;
                *reinterpret_cast<float2*>(outf + idx) = make_float2(x0, x1);
                *reinterpret_cast<__nv_bfloat162*>(outb + idx) =
                    __floats2bfloat162_rn(vr * x0, vr * x1);
            }
        }
    }
}

// ---------------- host -------------------------------------------------------
extern "C" void kernel_launch(void* const* d_in, const int* in_sizes, int n_in,
                              void* d_out, int out_size) {
    const float* x      = (const float*)d_in[0];
    const float* adj    = (const float*)d_in[1];
    const float* W_proj = (const float*)d_in[2];
    const float* b_proj = (const float*)d_in[3];
    const float* W_pi1  = (const float*)d_in[4];
    const float* b_pi1  = (const float*)d_in[5];
    const float* W_pi2  = (const float*)d_in[6];
    const float* b_pi2  = (const float*)d_in[7];
    const float* W_f    = (const float*)d_in[8];
    const float* b_f    = (const float*)d_in[9];
    const float* dt     = (const float*)d_in[10];
    float* out = (float*)d_out;
    (void)in_sizes; (void)n_in; (void)out_size;

    void *p_adjb, *p_xhi, *p_xlo, *p_wfhi, *p_wflo, *p_wprojb, *p_wpi1b;
    void *p_zb, *p_hb, *p_stb, *p_tgt, *p_q, *p_v, *p_d;
    cudaGetSymbolAddress(&p_adjb, g_adjb);
    cudaGetSymbolAddress(&p_xhi, g_Xhi);
    cudaGetSymbolAddress(&p_xlo, g_Xlo);
    cudaGetSymbolAddress(&p_wfhi, g_Wfhi);
    cudaGetSymbolAddress(&p_wflo, g_Wflo);
    cudaGetSymbolAddress(&p_wprojb, g_Wprojb);
    cudaGetSymbolAddress(&p_wpi1b, g_Wpi1b);
    cudaGetSymbolAddress(&p_zb, g_Zb);
    cudaGetSymbolAddress(&p_hb, g_Hb);
    cudaGetSymbolAddress(&p_stb, g_stb);
    cudaGetSymbolAddress(&p_tgt, g_target);
    cudaGetSymbolAddress(&p_q, g_q);
    cudaGetSymbolAddress(&p_v, g_v);
    cudaGetSymbolAddress(&p_d, g_d);

    bf16* adjb = (bf16*)p_adjb;
    bf16 *Xhi = (bf16*)p_xhi, *Xlo = (bf16*)p_xlo;
    bf16 *Wfhi = (bf16*)p_wfhi, *Wflo = (bf16*)p_wflo;
    bf16 *Wprojb = (bf16*)p_wprojb, *Wpi1b = (bf16*)p_wpi1b;
    bf16 *Zb = (bf16*)p_zb, *Hb = (bf16*)p_hb, *stb = (bf16*)p_stb;
    float *tgt = (float*)p_tgt, *q = (float*)p_q, *v = (float*)p_v, *d = (float*)p_d;

    // 1. conversions
    k_split<<<(NN * CC + 255) / 256, 256>>>(x, Xhi, Xlo, NN * CC);
    k_split<<<(CC * CC + 255) / 256, 256>>>(W_f, Wfhi, Wflo, CC * CC);
    k_f2b<<<(CC * LL + 255) / 256, 256>>>(W_proj, Wprojb, CC * LL);
    k_f2b<<<(LL * CC + 255) / 256, 256>>>(W_pi1, Wpi1b, LL * CC);

    // 2. row sums q + adj -> bf16
    k_rowsum_convert<<<NN, 256>>>(adj, adjb, q);

    // 3. Z = x @ W_proj + b_proj        [4096,64] (bf16 inputs fine for pi path)
    gemm_bf16<128, 64, 32, 4, 2, 0><<<dim3(NN / 128, 1), 256>>>(
        Xhi, Wprojb, NN, LL, CC, b_proj, nullptr, nullptr, nullptr, nullptr, Zb);

    // 4. H = relu(Z @ W_pi1 + b_pi1)    [4096,512]
    gemm_bf16<128, 128, 32, 2, 4, 1><<<dim3(NN / 128, CC / 128), 256>>>(
        Zb, Wpi1b, NN, CC, LL, b_pi1, nullptr, nullptr, nullptr, nullptr, Hb);

    // 5. pi, v = pi/q
    k_pi<<<NN, 128>>>(Hb, W_pi2, b_pi2, q, v);

    // 6. target = relu(x @ W_f + b_f) fp32-accurate (split bf16x3); st = v*target
    gemm_split3<128, 128, 32, 2, 4><<<dim3(NN / 128, CC / 128), 256>>>(
        Xhi, Xlo, Wfhi, Wflo, NN, CC, CC, b_f, v, tgt, stb);

    // 7. d = adjb @ v + 1e-5
    k_dvec<<<NN, 256>>>(adjb, v, d);

    // 8. out = (1-dt)*target + (dt/(eps*d[i])) * (adjb @ st)
    gemm_bf16<128, 128, 32, 2, 4, 3><<<dim3(NN / 128, CC / 128), 256>>>(
        adjb, stb, NN, CC, NN, nullptr, d, tgt, dt, out, nullptr);
}

// round 4
// speedup vs baseline: 1.0025x; 1.0025x over previous
#include <cuda_runtime.h>
#include <cuda_bf16.h>
#include <cstdint>
#include <math.h>

typedef __nv_bfloat16 bf16;

#define NN 4096
#define CC 512
#define LL 64

// ---------------- scratch (device globals: no allocations allowed) ----------
__device__ bf16  g_adjb[(size_t)NN * NN];     // 32 MB  adj in bf16
__device__ bf16  g_Xhi[NN * CC];
__device__ bf16  g_Xlo[NN * CC];
__device__ bf16  g_Wfhi[CC * CC];
__device__ bf16  g_Wflo[CC * CC];
__device__ bf16  g_Wprojb[CC * LL];
__device__ bf16  g_Wpi1b[LL * CC];
__device__ bf16  g_Zb[NN * LL];
__device__ bf16  g_Hb[NN * CC];
__device__ bf16  g_stb[NN * CC];              // v[row] * target, bf16
__device__ float g_target[NN * CC];           // fp32 target
__device__ float g_q[NN];
__device__ float g_v[NN];
__device__ float g_d[NN];

// ---------------- PTX helpers ----------------------------------------------
__device__ __forceinline__ uint32_t smem_u32(const void* p) {
    return (uint32_t)__cvta_generic_to_shared(p);
}
__device__ __forceinline__ void cp_async16(uint32_t s, const void* g) {
    asm volatile("cp.async.cg.shared.global [%0], [%1], 16;\n" :: "r"(s), "l"(g) : "memory");
}
__device__ __forceinline__ void cp_commit() {
    asm volatile("cp.async.commit_group;\n" ::: "memory");
}
__device__ __forceinline__ void cp_wait0() {
    asm volatile("cp.async.wait_group 0;\n" ::: "memory");
}
__device__ __forceinline__ void ldsm_x4(uint32_t* r, uint32_t a) {
    asm volatile("ldmatrix.sync.aligned.m8n8.x4.shared.b16 {%0,%1,%2,%3}, [%4];"
                 : "=r"(r[0]), "=r"(r[1]), "=r"(r[2]), "=r"(r[3]) : "r"(a));
}
__device__ __forceinline__ void ldsm_x2t(uint32_t* r, uint32_t a) {
    asm volatile("ldmatrix.sync.aligned.m8n8.x2.trans.shared.b16 {%0,%1}, [%2];"
                 : "=r"(r[0]), "=r"(r[1]) : "r"(a));
}
__device__ __forceinline__ void mma_bf16(float* c, const uint32_t* a, const uint32_t* b) {
    asm volatile("mma.sync.aligned.m16n8k16.row.col.f32.bf16.bf16.f32 "
                 "{%0,%1,%2,%3}, {%4,%5,%6,%7}, {%8,%9}, {%0,%1,%2,%3};"
                 : "+f"(c[0]), "+f"(c[1]), "+f"(c[2]), "+f"(c[3])
                 : "r"(a[0]), "r"(a[1]), "r"(a[2]), "r"(a[3]), "r"(b[0]), "r"(b[1]));
}

// ---------------- small conversion kernels ----------------------------------
__global__ void k_f2b(const float* __restrict__ s, bf16* __restrict__ d, int n) {
    int i = blockIdx.x * blockDim.x + threadIdx.x;
    if (i < n) d[i] = __float2bfloat16(s[i]);
}
__global__ void k_split(const float* __restrict__ s, bf16* __restrict__ hi,
                        bf16* __restrict__ lo, int n) {
    int i = blockIdx.x * blockDim.x + threadIdx.x;
    if (i < n) {
        float f = s[i];
        bf16 h = __float2bfloat16(f);
        hi[i] = h;
        lo[i] = __float2bfloat16(f - __bfloat162float(h));
    }
}

// q[i] = sum_j adj[i,j]  (fp32), and convert adj -> bf16
__global__ void k_rowsum_convert(const float* __restrict__ adj,
                                 bf16* __restrict__ adjb, float* __restrict__ q) {
    int row = blockIdx.x, t = threadIdx.x;  // 256 threads
    const float4* src = reinterpret_cast<const float4*>(adj + (size_t)row * NN);
    uint2* dst = reinterpret_cast<uint2*>(adjb + (size_t)row * NN);
    float s = 0.f;
#pragma unroll
    for (int i = 0; i < 4; i++) {
        float4 f = src[t + i * 256];
        s += (f.x + f.y) + (f.z + f.w);
        __nv_bfloat162 b0 = __floats2bfloat162_rn(f.x, f.y);
        __nv_bfloat162 b1 = __floats2bfloat162_rn(f.z, f.w);
        uint2 u;
        u.x = *reinterpret_cast<uint32_t*>(&b0);
        u.y = *reinterpret_cast<uint32_t*>(&b1);
        dst[t + i * 256] = u;
    }
    for (int o = 16; o > 0; o >>= 1) s += __shfl_xor_sync(0xffffffffu, s, o);
    __shared__ float ws[8];
    if ((t & 31) == 0) ws[t >> 5] = s;
    __syncthreads();
    if (t == 0) {
        float tot = 0.f;
#pragma unroll
        for (int i = 0; i < 8; i++) tot += ws[i];
        q[row] = tot;
    }
}

// pi per row: sigmoid(H[row,:] . W_pi2 + b_pi2); v = pi / q
__global__ void k_pi(const bf16* __restrict__ H, const float* __restrict__ W2,
                     const float* __restrict__ b2, const float* __restrict__ q,
                     float* __restrict__ v) {
    int row = blockIdx.x, t = threadIdx.x;  // 128 threads
    uint2 u = reinterpret_cast<const uint2*>(H + (size_t)row * CC)[t];
    float4 w = reinterpret_cast<const float4*>(W2)[t];
    __nv_bfloat162 p0 = *reinterpret_cast<__nv_bfloat162*>(&u.x);
    __nv_bfloat162 p1 = *reinterpret_cast<__nv_bfloat162*>(&u.y);
    float s = __bfloat162float(p0.x) * w.x + __bfloat162float(p0.y) * w.y +
              __bfloat162float(p1.x) * w.z + __bfloat162float(p1.y) * w.w;
    for (int o = 16; o > 0; o >>= 1) s += __shfl_xor_sync(0xffffffffu, s, o);
    __shared__ float ws[4];
    if ((t & 31) == 0) ws[t >> 5] = s;
    __syncthreads();
    if (t == 0) {
        s = ws[0] + ws[1] + ws[2] + ws[3] + b2[0];
        float pi = 1.f / (1.f + expf(-s));
        v[row] = pi / q[row];
    }
}

// d[i] = sum_j adjb[i,j] * v[j] + 1e-5
__global__ void k_dvec(const bf16* __restrict__ adjb, const float* __restrict__ v,
                       float* __restrict__ d) {
    int row = blockIdx.x, t = threadIdx.x;  // 256 threads
    const uint4* ap = reinterpret_cast<const uint4*>(adjb + (size_t)row * NN);
    float s = 0.f;
#pragma unroll
    for (int i = 0; i < 2; i++) {
        int ci = t + i * 256;  // chunk of 8 bf16
        uint4 u = ap[ci];
        const float4* vp = reinterpret_cast<const float4*>(v + ci * 8);
        float4 v0 = vp[0], v1 = vp[1];
        __nv_bfloat162 a0 = *reinterpret_cast<__nv_bfloat162*>(&u.x);
        __nv_bfloat162 a1 = *reinterpret_cast<__nv_bfloat162*>(&u.y);
        __nv_bfloat162 a2 = *reinterpret_cast<__nv_bfloat162*>(&u.z);
        __nv_bfloat162 a3 = *reinterpret_cast<__nv_bfloat162*>(&u.w);
        s += __bfloat162float(a0.x) * v0.x + __bfloat162float(a0.y) * v0.y +
             __bfloat162float(a1.x) * v0.z + __bfloat162float(a1.y) * v0.w +
             __bfloat162float(a2.x) * v1.x + __bfloat162float(a2.y) * v1.y +
             __bfloat162float(a3.x) * v1.z + __bfloat162float(a3.y) * v1.w;
    }
    for (int o = 16; o > 0; o >>= 1) s += __shfl_xor_sync(0xffffffffu, s, o);
    __shared__ float ws[8];
    if ((t & 31) == 0) ws[t >> 5] = s;
    __syncthreads();
    if (t == 0) {
        float tot = 0.f;
#pragma unroll
        for (int i = 0; i < 8; i++) tot += ws[i];
        d[row] = tot + 1e-5f;
    }
}

// ---------------- generic bf16 mma GEMM (2-stage cp.async pipeline) ----------
// EPI: 0 = +bias -> bf16      (Z)
//      1 = relu(+bias) -> bf16 (H)
//      3 = out = (1-dt)*target + (dt/(0.25*d[row]))*acc  (final)
template <int BM, int BN, int BK, int WMC, int WNC, int EPI>
__global__ void __launch_bounds__(256)
gemm_bf16(const bf16* __restrict__ A, const bf16* __restrict__ B,
          int M, int N, int K,
          const float* __restrict__ bias, const float* __restrict__ dvec,
          const float* __restrict__ tgt, const float* __restrict__ dtp,
          float* __restrict__ outf, bf16* __restrict__ outb) {
    constexpr int WARP_M = BM / WMC, WARP_N = BN / WNC;
    constexpr int FM = WARP_M / 16, FN = WARP_N / 8;
    constexpr int LDA = BK + 8, LDB = BN + 8;
    __shared__ __align__(16) bf16 As[2][BM * LDA];
    __shared__ __align__(16) bf16 Bs[2][BK * LDB];

    const int tid = threadIdx.x, lane = tid & 31, warp = tid >> 5;
    const int wm = warp / WNC, wn = warp % WNC;
    const int bm0 = blockIdx.x * BM, bn0 = blockIdx.y * BN;
    constexpr int ACH = BM * BK / 8, BCH = BK * BN / 8;
    constexpr int ACPR = BK / 8, BCPR = BN / 8;

    float acc[FM][FN][4];
#pragma unroll
    for (int i = 0; i < FM; i++)
#pragma unroll
        for (int j = 0; j < FN; j++)
#pragma unroll
            for (int k = 0; k < 4; k++) acc[i][j][k] = 0.f;

    auto load_tiles = [&](int kt, int buf) {
        for (int c = tid; c < ACH; c += 256) {
            int r = c / ACPR, co = (c % ACPR) * 8;
            cp_async16(smem_u32(&As[buf][r * LDA + co]),
                       A + (size_t)(bm0 + r) * K + (size_t)kt * BK + co);
        }
        for (int c = tid; c < BCH; c += 256) {
            int r = c / BCPR, co = (c % BCPR) * 8;
            cp_async16(smem_u32(&Bs[buf][r * LDB + co]),
                       B + (size_t)(kt * BK + r) * N + bn0 + co);
        }
    };

    const int KT = K / BK;
    load_tiles(0, 0);
    cp_commit();
    for (int it = 0; it < KT; ++it) {
        int buf = it & 1;
        cp_wait0();
        __syncthreads();
        if (it + 1 < KT) {
            load_tiles(it + 1, buf ^ 1);
            cp_commit();
        }
#pragma unroll
        for (int kk = 0; kk < BK / 16; ++kk) {
            uint32_t af[FM][4], bfr[FN][2];
#pragma unroll
            for (int i = 0; i < FM; i++) {
                int r = wm * WARP_M + i * 16 + (lane & 15);
                int cc = kk * 16 + ((lane >> 4) << 3);
                ldsm_x4(af[i], smem_u32(&As[buf][r * LDA + cc]));
            }
#pragma unroll
            for (int j = 0; j < FN; j++) {
                int r = kk * 16 + (lane & 15);
                int cc = wn * WARP_N + j * 8;
                ldsm_x2t(bfr[j], smem_u32(&Bs[buf][r * LDB + cc]));
            }
#pragma unroll
            for (int i = 0; i < FM; i++)
#pragma unroll
                for (int j = 0; j < FN; j++) mma_bf16(acc[i][j], af[i], bfr[j]);
        }
    }

    // epilogue
    float dt1 = 0.f, mdt = 0.f;
    if constexpr (EPI == 3) {
        dt1 = dtp[0];
        mdt = 1.f - dt1;
    }
#pragma unroll
    for (int i = 0; i < FM; i++) {
        int rbase = bm0 + wm * WARP_M + i * 16 + (lane >> 2);
#pragma unroll
        for (int h = 0; h < 2; h++) {
            int r = rbase + h * 8;
            float rs = 0.f;
            if constexpr (EPI == 3) rs = dt1 / (0.25f * dvec[r]);
#pragma unroll
            for (int j = 0; j < FN; j++) {
                int c = bn0 + wn * WARP_N + j * 8 + (lane & 3) * 2;
                float x0 = acc[i][j][h * 2 + 0], x1 = acc[i][j][h * 2 + 1];
                size_t idx = (size_t)r * N + c;
                if constexpr (EPI == 0) {
                    x0 += bias[c];
                    x1 += bias[c + 1];
                    *reinterpret_cast<__nv_bfloat162*>(outb + idx) =
                        __floats2bfloat162_rn(x0, x1);
                } else if constexpr (EPI == 1) {
                    x0 = fmaxf(x0 + bias[c], 0.f);
                    x1 = fmaxf(x1 + bias[c + 1], 0.f);
                    *reinterpret_cast<__nv_bfloat162*>(outb + idx) =
                        __floats2bfloat162_rn(x0, x1);
                } else {
                    float2 tg = *reinterpret_cast<const float2*>(tgt + idx);
                    float2 o;
                    o.x = mdt * tg.x + rs * x0;
                    o.y = mdt * tg.y + rs * x1;
                    *reinterpret_cast<float2*>(outf + idx) = o;
                }
            }
        }
    }
}

// ---------------- split-bf16 (hi/lo) GEMM for target: fp32-accurate ---------
// acc = Ah*Bh + Ah*Bl + Al*Bh ; epilogue: target fp32 + st = v[row]*target bf16
template <int BM, int BN, int BK, int WMC, int WNC>
__global__ void __launch_bounds__(256)
gemm_split3(const bf16* __restrict__ Ah, const bf16* __restrict__ Al,
            const bf16* __restrict__ Bh, const bf16* __restrict__ Bl,
            int M, int N, int K,
            const float* __restrict__ bias, const float* __restrict__ vvec,
            float* __restrict__ outf, bf16* __restrict__ outb) {
    constexpr int WARP_M = BM / WMC, WARP_N = BN / WNC;
    constexpr int FM = WARP_M / 16, FN = WARP_N / 8;
    constexpr int LDA = BK + 8, LDB = BN + 8;
    __shared__ __align__(16) bf16 As[2][BM * LDA];  // [0]=hi [1]=lo
    __shared__ __align__(16) bf16 Bs[2][BK * LDB];

    const int tid = threadIdx.x, lane = tid & 31, warp = tid >> 5;
    const int wm = warp / WNC, wn = warp % WNC;
    const int bm0 = blockIdx.x * BM, bn0 = blockIdx.y * BN;
    constexpr int ACH = BM * BK / 8, BCH = BK * BN / 8;
    constexpr int ACPR = BK / 8, BCPR = BN / 8;

    float acc[FM][FN][4];
#pragma unroll
    for (int i = 0; i < FM; i++)
#pragma unroll
        for (int j = 0; j < FN; j++)
#pragma unroll
            for (int k = 0; k < 4; k++) acc[i][j][k] = 0.f;

    const int KT = K / BK;
    for (int it = 0; it < KT; ++it) {
        if (it > 0) __syncthreads();
        for (int c = tid; c < ACH; c += 256) {
            int r = c / ACPR, co = (c % ACPR) * 8;
            size_t g = (size_t)(bm0 + r) * K + (size_t)it * BK + co;
            cp_async16(smem_u32(&As[0][r * LDA + co]), Ah + g);
            cp_async16(smem_u32(&As[1][r * LDA + co]), Al + g);
        }
        for (int c = tid; c < BCH; c += 256) {
            int r = c / BCPR, co = (c % BCPR) * 8;
            size_t g = (size_t)(it * BK + r) * N + bn0 + co;
            cp_async16(smem_u32(&Bs[0][r * LDB + co]), Bh + g);
            cp_async16(smem_u32(&Bs[1][r * LDB + co]), Bl + g);
        }
        cp_commit();
        cp_wait0();
        __syncthreads();
#pragma unroll
        for (int kk = 0; kk < BK / 16; ++kk) {
            uint32_t ah[FM][4], al[FM][4], bh[FN][2], bl[FN][2];
#pragma unroll
            for (int i = 0; i < FM; i++) {
                int r = wm * WARP_M + i * 16 + (lane & 15);
                int cc = kk * 16 + ((lane >> 4) << 3);
                ldsm_x4(ah[i], smem_u32(&As[0][r * LDA + cc]));
                ldsm_x4(al[i], smem_u32(&As[1][r * LDA + cc]));
            }
#pragma unroll
            for (int j = 0; j < FN; j++) {
                int r = kk * 16 + (lane & 15);
                int cc = wn * WARP_N + j * 8;
                ldsm_x2t(bh[j], smem_u32(&Bs[0][r * LDB + cc]));
                ldsm_x2t(bl[j], smem_u32(&Bs[1][r * LDB + cc]));
            }
#pragma unroll
            for (int i = 0; i < FM; i++)
#pragma unroll
                for (int j = 0; j < FN; j++) {
                    mma_bf16(acc[i][j], ah[i], bh[j]);
                    mma_bf16(acc[i][j], ah[i], bl[j]);
                    mma_bf16(acc[i][j], al[i], bh[j]);
                }
        }
    }

#pragma unroll
    for (int i = 0; i < FM; i++) {
        int rbase = bm0 + wm * WARP_M + i * 16 + (lane >> 2);
#pragma unroll
        for (int h = 0; h < 2; h++) {
            int r = rbase + h * 8;
            float vr = vvec[r];
#pragma unroll
            for (int j = 0; j < FN; j++) {
                int c = bn0 + wn * WARP_N + j * 8 + (lane & 3) * 2;
                float x0 = fmaxf(acc[i][j][h * 2 + 0] + bias[c], 0.f);
                float x1 = fmaxf(acc[i][j][h * 2 + 1] + bias[c + 1], 0.f);
                size_t idx = (size_t)r * N + c;
                *reinterpret_cast<float2*>(outf + idx) = make_float2(x0, x1);
                *reinterpret_cast<__nv_bfloat162*>(outb + idx) =
                    __floats2bfloat162_rn(vr * x0, vr * x1);
            }
        }
    }
}

// ---------------- host -------------------------------------------------------
extern "C" void kernel_launch(void* const* d_in, const int* in_sizes, int n_in,
                              void* d_out, int out_size) {
    const float* x      = (const float*)d_in[0];
    const float* adj    = (const float*)d_in[1];
    const float* W_proj = (const float*)d_in[2];
    const float* b_proj = (const float*)d_in[3];
    const float* W_pi1  = (const float*)d_in[4];
    const float* b_pi1  = (const float*)d_in[5];
    const float* W_pi2  = (const float*)d_in[6];
    const float* b_pi2  = (const float*)d_in[7];
    const float* W_f    = (const float*)d_in[8];
    const float* b_f    = (const float*)d_in[9];
    const float* dt     = (const float*)d_in[10];
    float* out = (float*)d_out;
    (void)in_sizes; (void)n_in; (void)out_size;

    void *p_adjb, *p_xhi, *p_xlo, *p_wfhi, *p_wflo, *p_wprojb, *p_wpi1b;
    void *p_zb, *p_hb, *p_stb, *p_tgt, *p_q, *p_v, *p_d;
    cudaGetSymbolAddress(&p_adjb, g_adjb);
    cudaGetSymbolAddress(&p_xhi, g_Xhi);
    cudaGetSymbolAddress(&p_xlo, g_Xlo);
    cudaGetSymbolAddress(&p_wfhi, g_Wfhi);
    cudaGetSymbolAddress(&p_wflo, g_Wflo);
    cudaGetSymbolAddress(&p_wprojb, g_Wprojb);
    cudaGetSymbolAddress(&p_wpi1b, g_Wpi1b);
    cudaGetSymbolAddress(&p_zb, g_Zb);
    cudaGetSymbolAddress(&p_hb, g_Hb);
    cudaGetSymbolAddress(&p_stb, g_stb);
    cudaGetSymbolAddress(&p_tgt, g_target);
    cudaGetSymbolAddress(&p_q, g_q);
    cudaGetSymbolAddress(&p_v, g_v);
    cudaGetSymbolAddress(&p_d, g_d);

    bf16* adjb = (bf16*)p_adjb;
    bf16 *Xhi = (bf16*)p_xhi, *Xlo = (bf16*)p_xlo;
    bf16 *Wfhi = (bf16*)p_wfhi, *Wflo = (bf16*)p_wflo;
    bf16 *Wprojb = (bf16*)p_wprojb, *Wpi1b = (bf16*)p_wpi1b;
    bf16 *Zb = (bf16*)p_zb, *Hb = (bf16*)p_hb, *stb = (bf16*)p_stb;
    float *tgt = (float*)p_tgt, *q = (float*)p_q, *v = (float*)p_v, *d = (float*)p_d;

    // 1. conversions
    k_split<<<(NN * CC + 255) / 256, 256>>>(x, Xhi, Xlo, NN * CC);
    k_split<<<(CC * CC + 255) / 256, 256>>>(W_f, Wfhi, Wflo, CC * CC);
    k_f2b<<<(CC * LL + 255) / 256, 256>>>(W_proj, Wprojb, CC * LL);
    k_f2b<<<(LL * CC + 255) / 256, 256>>>(W_pi1, Wpi1b, LL * CC);

    // 2. row sums q + adj -> bf16
    k_rowsum_convert<<<NN, 256>>>(adj, adjb, q);

    // 3. Z = x @ W_proj + b_proj        [4096,64] (bf16 inputs fine for pi path)
    gemm_bf16<128, 64, 32, 4, 2, 0><<<dim3(NN / 128, 1), 256>>>(
        Xhi, Wprojb, NN, LL, CC, b_proj, nullptr, nullptr, nullptr, nullptr, Zb);

    // 4. H = relu(Z @ W_pi1 + b_pi1)    [4096,512]
    gemm_bf16<128, 128, 32, 2, 4, 1><<<dim3(NN / 128, CC / 128), 256>>>(
        Zb, Wpi1b, NN, CC, LL, b_pi1, nullptr, nullptr, nullptr, nullptr, Hb);

    // 5. pi, v = pi/q
    k_pi<<<NN, 128>>>(Hb, W_pi2, b_pi2, q, v);

    // 6. target = relu(x @ W_f + b_f) fp32-accurate (split bf16x3); st = v*target
    gemm_split3<128, 128, 32, 2, 4><<<dim3(NN / 128, CC / 128), 256>>>(
        Xhi, Xlo, Wfhi, Wflo, NN, CC, CC, b_f, v, tgt, stb);

    // 7. d = adjb @ v + 1e-5
    k_dvec<<<NN, 256>>>(adjb, v, d);

    // 8. out = (1-dt)*target + (dt/(eps*d[i])) * (adjb @ st)
    gemm_bf16<128, 128, 32, 2, 4, 3><<<dim3(NN / 128, CC / 128), 256>>>(
        adjb, stb, NN, CC, NN, nullptr, d, tgt, dt, out, nullptr);
}

// round 6
// speedup vs baseline: 1.2538x; 1.2507x over previous
#include <cuda_runtime.h>
#include <cuda_bf16.h>
#include <cstdint>
#include <math.h>

typedef __nv_bfloat16 bf16;

#define NN 4096
#define CC 512
#define LL 64

// ---------------- scratch (device globals: no allocations allowed) ----------
__device__ bf16  g_adjb[(size_t)NN * NN];     // 32 MB  adj in bf16
__device__ bf16  g_Xhi[NN * CC];
__device__ bf16  g_Xlo[NN * CC];
__device__ bf16  g_Wfhi[CC * CC];
__device__ bf16  g_Wflo[CC * CC];
__device__ bf16  g_Wprojb[CC * LL];
__device__ bf16  g_Wpi1b[LL * CC];
__device__ bf16  g_Zb[NN * LL];
__device__ bf16  g_Hb[NN * CC];
__device__ bf16  g_stb[NN * CC];              // v[row] * target, bf16 (row-major)
__device__ float g_target[NN * CC];           // fp32 target
__device__ float g_q[NN];
__device__ float g_v[NN];
__device__ float g_d[NN];

// ---------------- PTX helpers ----------------------------------------------
__device__ __forceinline__ uint32_t smem_u32(const void* p) {
    return (uint32_t)__cvta_generic_to_shared(p);
}
__device__ __forceinline__ void cp_async16(uint32_t s, const void* g) {
    asm volatile("cp.async.cg.shared.global [%0], [%1], 16;\n" :: "r"(s), "l"(g) : "memory");
}
__device__ __forceinline__ void cp_commit() {
    asm volatile("cp.async.commit_group;\n" ::: "memory");
}
__device__ __forceinline__ void cp_wait0() {
    asm volatile("cp.async.wait_group 0;\n" ::: "memory");
}
__device__ __forceinline__ void cp_wait1() {
    asm volatile("cp.async.wait_group 1;\n" ::: "memory");
}
__device__ __forceinline__ void ldsm_x4(uint32_t* r, uint32_t a) {
    asm volatile("ldmatrix.sync.aligned.m8n8.x4.shared.b16 {%0,%1,%2,%3}, [%4];"
                 : "=r"(r[0]), "=r"(r[1]), "=r"(r[2]), "=r"(r[3]) : "r"(a));
}
__device__ __forceinline__ void ldsm_x2t(uint32_t* r, uint32_t a) {
    asm volatile("ldmatrix.sync.aligned.m8n8.x2.trans.shared.b16 {%0,%1}, [%2];"
                 : "=r"(r[0]), "=r"(r[1]) : "r"(a));
}
__device__ __forceinline__ void mma_bf16(float* c, const uint32_t* a, const uint32_t* b) {
    asm volatile("mma.sync.aligned.m16n8k16.row.col.f32.bf16.bf16.f32 "
                 "{%0,%1,%2,%3}, {%4,%5,%6,%7}, {%8,%9}, {%0,%1,%2,%3};"
                 : "+f"(c[0]), "+f"(c[1]), "+f"(c[2]), "+f"(c[3])
                 : "r"(a[0]), "r"(a[1]), "r"(a[2]), "r"(a[3]), "r"(b[0]), "r"(b[1]));
}

// ---------------- fused pre-kernel: rowsum+convert(adj) AND bf16 conversions --
// blocks [0, NN): row sums of adj + adj->bf16
// blocks [NN, ...): x split, W_f split, W_proj/W_pi1 conversion
__global__ void k_pre(const float* __restrict__ adj, bf16* __restrict__ adjb,
                      float* __restrict__ q,
                      const float* __restrict__ x, const float* __restrict__ Wf,
                      const float* __restrict__ Wp, const float* __restrict__ Wp1,
                      bf16* __restrict__ Xhi, bf16* __restrict__ Xlo,
                      bf16* __restrict__ Wfhi, bf16* __restrict__ Wflo,
                      bf16* __restrict__ Wpb, bf16* __restrict__ Wp1b) {
    int t = threadIdx.x;
    if (blockIdx.x < NN) {
        int row = blockIdx.x;
        const float4* src = reinterpret_cast<const float4*>(adj + (size_t)row * NN);
        uint2* dst = reinterpret_cast<uint2*>(adjb + (size_t)row * NN);
        float s = 0.f;
#pragma unroll
        for (int i = 0; i < 4; i++) {
            float4 f = src[t + i * 256];
            s += (f.x + f.y) + (f.z + f.w);
            __nv_bfloat162 b0 = __floats2bfloat162_rn(f.x, f.y);
            __nv_bfloat162 b1 = __floats2bfloat162_rn(f.z, f.w);
            uint2 u;
            u.x = *reinterpret_cast<uint32_t*>(&b0);
            u.y = *reinterpret_cast<uint32_t*>(&b1);
            dst[t + i * 256] = u;
        }
        for (int o = 16; o > 0; o >>= 1) s += __shfl_xor_sync(0xffffffffu, s, o);
        __shared__ float ws[8];
        if ((t & 31) == 0) ws[t >> 5] = s;
        __syncthreads();
        if (t == 0) {
            float tot = 0.f;
#pragma unroll
            for (int i = 0; i < 8; i++) tot += ws[i];
            q[row] = tot;
        }
        return;
    }
    int i = (blockIdx.x - NN) * 256 + t;
    const int e0 = NN * CC;
    const int e1 = e0 + CC * CC;
    const int e2 = e1 + CC * LL;
    const int e3 = e2 + LL * CC;
    if (i < e0) {
        float f = x[i];
        bf16 h = __float2bfloat16(f);
        Xhi[i] = h;
        Xlo[i] = __float2bfloat16(f - __bfloat162float(h));
    } else if (i < e1) {
        int j = i - e0;
        float f = Wf[j];
        bf16 h = __float2bfloat16(f);
        Wfhi[j] = h;
        Wflo[j] = __float2bfloat16(f - __bfloat162float(h));
    } else if (i < e2) {
        int j = i - e1;
        Wpb[j] = __float2bfloat16(Wp[j]);
    } else if (i < e3) {
        int j = i - e2;
        Wp1b[j] = __float2bfloat16(Wp1[j]);
    }
}

// pi per row: sigmoid(H[row,:] . W_pi2 + b_pi2); v = pi / q
__global__ void k_pi(const bf16* __restrict__ H, const float* __restrict__ W2,
                     const float* __restrict__ b2, const float* __restrict__ q,
                     float* __restrict__ v) {
    int row = blockIdx.x, t = threadIdx.x;  // 128 threads
    uint2 u = reinterpret_cast<const uint2*>(H + (size_t)row * CC)[t];
    float4 w = reinterpret_cast<const float4*>(W2)[t];
    __nv_bfloat162 p0 = *reinterpret_cast<__nv_bfloat162*>(&u.x);
    __nv_bfloat162 p1 = *reinterpret_cast<__nv_bfloat162*>(&u.y);
    float s = __bfloat162float(p0.x) * w.x + __bfloat162float(p0.y) * w.y +
              __bfloat162float(p1.x) * w.z + __bfloat162float(p1.y) * w.w;
    for (int o = 16; o > 0; o >>= 1) s += __shfl_xor_sync(0xffffffffu, s, o);
    __shared__ float ws[4];
    if ((t & 31) == 0) ws[t >> 5] = s;
    __syncthreads();
    if (t == 0) {
        s = ws[0] + ws[1] + ws[2] + ws[3] + b2[0];
        float pi = 1.f / (1.f + expf(-s));
        v[row] = pi / q[row];
    }
}

// d[i] = sum_j adjb[i,j] * v[j] + 1e-5
__global__ void k_dvec(const bf16* __restrict__ adjb, const float* __restrict__ v,
                       float* __restrict__ d) {
    int row = blockIdx.x, t = threadIdx.x;  // 256 threads
    const uint4* ap = reinterpret_cast<const uint4*>(adjb + (size_t)row * NN);
    float s = 0.f;
#pragma unroll
    for (int i = 0; i < 2; i++) {
        int ci = t + i * 256;  // chunk of 8 bf16
        uint4 u = ap[ci];
        const float4* vp = reinterpret_cast<const float4*>(v + ci * 8);
        float4 v0 = vp[0], v1 = vp[1];
        __nv_bfloat162 a0 = *reinterpret_cast<__nv_bfloat162*>(&u.x);
        __nv_bfloat162 a1 = *reinterpret_cast<__nv_bfloat162*>(&u.y);
        __nv_bfloat162 a2 = *reinterpret_cast<__nv_bfloat162*>(&u.z);
        __nv_bfloat162 a3 = *reinterpret_cast<__nv_bfloat162*>(&u.w);
        s += __bfloat162float(a0.x) * v0.x + __bfloat162float(a0.y) * v0.y +
             __bfloat162float(a1.x) * v0.z + __bfloat162float(a1.y) * v0.w +
             __bfloat162float(a2.x) * v1.x + __bfloat162float(a2.y) * v1.y +
             __bfloat162float(a3.x) * v1.z + __bfloat162float(a3.y) * v1.w;
    }
    for (int o = 16; o > 0; o >>= 1) s += __shfl_xor_sync(0xffffffffu, s, o);
    __shared__ float ws[8];
    if ((t & 31) == 0) ws[t >> 5] = s;
    __syncthreads();
    if (t == 0) {
        float tot = 0.f;
#pragma unroll
        for (int i = 0; i < 8; i++) tot += ws[i];
        d[row] = tot + 1e-5f;
    }
}

// ---------------- generic bf16 mma GEMM (small GEMMs: Z and H) ---------------
// EPI: 0 = +bias -> bf16 ; 1 = relu(+bias) -> bf16
template <int BM, int BN, int BK, int WMC, int WNC, int EPI>
__global__ void __launch_bounds__(256)
gemm_bf16(const bf16* __restrict__ A, const bf16* __restrict__ B,
          int M, int N, int K,
          const float* __restrict__ bias, bf16* __restrict__ outb) {
    constexpr int WARP_M = BM / WMC, WARP_N = BN / WNC;
    constexpr int FM = WARP_M / 16, FN = WARP_N / 8;
    constexpr int LDA = BK + 8, LDB = BN + 8;
    __shared__ __align__(16) bf16 As[2][BM * LDA];
    __shared__ __align__(16) bf16 Bs[2][BK * LDB];

    const int tid = threadIdx.x, lane = tid & 31, warp = tid >> 5;
    const int wm = warp / WNC, wn = warp % WNC;
    const int bm0 = blockIdx.x * BM, bn0 = blockIdx.y * BN;
    constexpr int ACH = BM * BK / 8, BCH = BK * BN / 8;
    constexpr int ACPR = BK / 8, BCPR = BN / 8;

    float acc[FM][FN][4];
#pragma unroll
    for (int i = 0; i < FM; i++)
#pragma unroll
        for (int j = 0; j < FN; j++)
#pragma unroll
            for (int k = 0; k < 4; k++) acc[i][j][k] = 0.f;

    auto load_tiles = [&](int kt, int buf) {
        for (int c = tid; c < ACH; c += 256) {
            int r = c / ACPR, co = (c % ACPR) * 8;
            cp_async16(smem_u32(&As[buf][r * LDA + co]),
                       A + (size_t)(bm0 + r) * K + (size_t)kt * BK + co);
        }
        for (int c = tid; c < BCH; c += 256) {
            int r = c / BCPR, co = (c % BCPR) * 8;
            cp_async16(smem_u32(&Bs[buf][r * LDB + co]),
                       B + (size_t)(kt * BK + r) * N + bn0 + co);
        }
    };

    const int KTL = K / BK;
    load_tiles(0, 0);
    cp_commit();
    for (int it = 0; it < KTL; ++it) {
        int buf = it & 1;
        cp_wait0();
        __syncthreads();
        if (it + 1 < KTL) {
            load_tiles(it + 1, buf ^ 1);
            cp_commit();
        }
#pragma unroll
        for (int kk = 0; kk < BK / 16; ++kk) {
            uint32_t af[FM][4], bfr[FN][2];
#pragma unroll
            for (int i = 0; i < FM; i++) {
                int r = wm * WARP_M + i * 16 + (lane & 15);
                int cc = kk * 16 + ((lane >> 4) << 3);
                ldsm_x4(af[i], smem_u32(&As[buf][r * LDA + cc]));
            }
#pragma unroll
            for (int j = 0; j < FN; j++) {
                int r = kk * 16 + (lane & 15);
                int cc = wn * WARP_N + j * 8;
                ldsm_x2t(bfr[j], smem_u32(&Bs[buf][r * LDB + cc]));
            }
#pragma unroll
            for (int i = 0; i < FM; i++)
#pragma unroll
                for (int j = 0; j < FN; j++) mma_bf16(acc[i][j], af[i], bfr[j]);
        }
    }

#pragma unroll
    for (int i = 0; i < FM; i++) {
        int rbase = bm0 + wm * WARP_M + i * 16 + (lane >> 2);
#pragma unroll
        for (int h = 0; h < 2; h++) {
            int r = rbase + h * 8;
#pragma unroll
            for (int j = 0; j < FN; j++) {
                int c = bn0 + wn * WARP_N + j * 8 + (lane & 3) * 2;
                float x0 = acc[i][j][h * 2 + 0] + bias[c];
                float x1 = acc[i][j][h * 2 + 1] + bias[c + 1];
                if constexpr (EPI == 1) {
                    x0 = fmaxf(x0, 0.f);
                    x1 = fmaxf(x1, 0.f);
                }
                *reinterpret_cast<__nv_bfloat162*>(outb + (size_t)r * N + c) =
                    __floats2bfloat162_rn(x0, x1);
            }
        }
    }
}

// ---------------- split-bf16 (hi/lo) GEMM for target: fp32-accurate ---------
// acc = Ah*Bh + Ah*Bl + Al*Bh ; 2-stage double-buffered pipeline.
// epilogue: target fp32 + stb[r, c] = v[r]*target (row-major)
// BM=128 BN=128 BK=32; dynamic smem: Ah[2][5120] Al[2][5120] Bh[2][4352] Bl[2][4352]
__global__ void __launch_bounds__(256)
gemm_split3(const bf16* __restrict__ Ah, const bf16* __restrict__ Al,
            const bf16* __restrict__ Bh, const bf16* __restrict__ Bl,
            const float* __restrict__ bias, const float* __restrict__ vvec,
            float* __restrict__ outf, bf16* __restrict__ outb) {
    constexpr int BM = 128, BN = 128, BK = 32, WMC = 2, WNC = 4;
    constexpr int WARP_M = BM / WMC, WARP_N = BN / WNC;   // 64, 32
    constexpr int FM = WARP_M / 16, FN = WARP_N / 8;      // 4, 4
    constexpr int LDA = BK + 8, LDB = BN + 8;             // 40, 136
    constexpr int ASTG = BM * LDA;                        // 5120
    constexpr int BSTG = BK * LDB;                        // 4352
    extern __shared__ __align__(16) char sm3[];
    bf16* Ahs = (bf16*)sm3;              // [2][ASTG]
    bf16* Als = Ahs + 2 * ASTG;
    bf16* Bhs = Als + 2 * ASTG;
    bf16* Bls = Bhs + 2 * BSTG;

    const int tid = threadIdx.x, lane = tid & 31, warp = tid >> 5;
    const int wm = warp / WNC, wn = warp % WNC;
    const int bm0 = blockIdx.x * BM, bn0 = blockIdx.y * BN;
    constexpr int ACH = BM * BK / 8, BCH = BK * BN / 8;   // 512, 512
    constexpr int ACPR = BK / 8, BCPR = BN / 8;           // 4, 16

    float acc[FM][FN][4];
#pragma unroll
    for (int i = 0; i < FM; i++)
#pragma unroll
        for (int j = 0; j < FN; j++)
#pragma unroll
            for (int k = 0; k < 4; k++) acc[i][j][k] = 0.f;

    auto load_tiles = [&](int kt, int buf) {
        for (int c = tid; c < ACH; c += 256) {
            int r = c / ACPR, co = (c % ACPR) * 8;
            size_t g = (size_t)(bm0 + r) * CC + (size_t)kt * BK + co;
            cp_async16(smem_u32(Ahs + buf * ASTG + r * LDA + co), Ah + g);
            cp_async16(smem_u32(Als + buf * ASTG + r * LDA + co), Al + g);
        }
        for (int c = tid; c < BCH; c += 256) {
            int r = c / BCPR, co = (c % BCPR) * 8;
            size_t g = (size_t)(kt * BK + r) * CC + bn0 + co;
            cp_async16(smem_u32(Bhs + buf * BSTG + r * LDB + co), Bh + g);
            cp_async16(smem_u32(Bls + buf * BSTG + r * LDB + co), Bl + g);
        }
    };

    const int KTL = CC / BK;   // 16
    load_tiles(0, 0);
    cp_commit();
    for (int it = 0; it < KTL; ++it) {
        int buf = it & 1;
        cp_wait0();
        __syncthreads();
        if (it + 1 < KTL) {
            load_tiles(it + 1, buf ^ 1);
            cp_commit();
        }
#pragma unroll
        for (int kk = 0; kk < BK / 16; ++kk) {
            uint32_t ahf[FM][4], alf[FM][4], bhf[FN][2], blf[FN][2];
#pragma unroll
            for (int i = 0; i < FM; i++) {
                int r = wm * WARP_M + i * 16 + (lane & 15);
                int cc = kk * 16 + ((lane >> 4) << 3);
                ldsm_x4(ahf[i], smem_u32(Ahs + buf * ASTG + r * LDA + cc));
                ldsm_x4(alf[i], smem_u32(Als + buf * ASTG + r * LDA + cc));
            }
#pragma unroll
            for (int j = 0; j < FN; j++) {
                int r = kk * 16 + (lane & 15);
                int cc = wn * WARP_N + j * 8;
                ldsm_x2t(bhf[j], smem_u32(Bhs + buf * BSTG + r * LDB + cc));
                ldsm_x2t(blf[j], smem_u32(Bls + buf * BSTG + r * LDB + cc));
            }
#pragma unroll
            for (int i = 0; i < FM; i++)
#pragma unroll
                for (int j = 0; j < FN; j++) {
                    mma_bf16(acc[i][j], ahf[i], bhf[j]);
                    mma_bf16(acc[i][j], ahf[i], blf[j]);
                    mma_bf16(acc[i][j], alf[i], bhf[j]);
                }
        }
    }

#pragma unroll
    for (int i = 0; i < FM; i++) {
        int rbase = bm0 + wm * WARP_M + i * 16 + (lane >> 2);
#pragma unroll
        for (int h = 0; h < 2; h++) {
            int r = rbase + h * 8;
            float vr = vvec[r];
#pragma unroll
            for (int j = 0; j < FN; j++) {
                int c = bn0 + wn * WARP_N + j * 8 + (lane & 3) * 2;
                float x0 = fmaxf(acc[i][j][h * 2 + 0] + bias[c], 0.f);
                float x1 = fmaxf(acc[i][j][h * 2 + 1] + bias[c + 1], 0.f);
                size_t idx = (size_t)r * CC + c;
                *reinterpret_cast<float2*>(outf + idx) = make_float2(x0, x1);
                *reinterpret_cast<__nv_bfloat162*>(outb + idx) =
                    __floats2bfloat162_rn(vr * x0, vr * x1);
            }
        }
    }
}

// ---------------- final GEMM: 3-stage pipelined mma.sync ---------------------
// out[m, n] = (1-dt)*tgt[m, n] + dt/(0.25*d[m]) * sum_k adjb[m, k] * stb[k, n]
// BM=128 BN=128 BK=64, 3 stages, cp.async.wait_group 1 keeps a tile in flight.
__global__ void __launch_bounds__(256, 1)
k_final(const bf16* __restrict__ A, const bf16* __restrict__ B,
        const float* __restrict__ dvec, const float* __restrict__ tgt,
        const float* __restrict__ dtp, float* __restrict__ outf) {
    constexpr int BM = 128, BN = 128, BK = 64, WMC = 2, WNC = 4;
    constexpr int WARP_M = BM / WMC, WARP_N = BN / WNC;   // 64, 32
    constexpr int FM = WARP_M / 16, FN = WARP_N / 8;      // 4, 4
    constexpr int LDA = BK + 8, LDB = BN + 8;             // 72, 136
    constexpr int ASTG = BM * LDA;                        // 9216
    constexpr int BSTG = BK * LDB;                        // 8704
    extern __shared__ __align__(16) char smf[];
    bf16* As = (bf16*)smf;               // [3][ASTG]
    bf16* Bs = As + 3 * ASTG;            // [3][BSTG]

    const int tid = threadIdx.x, lane = tid & 31, warp = tid >> 5;
    const int wm = warp / WNC, wn = warp % WNC;
    const int bm0 = blockIdx.x * BM, bn0 = blockIdx.y * BN;
    constexpr int ACH = BM * BK / 8, BCH = BK * BN / 8;   // 1024, 1024
    constexpr int ACPR = BK / 8, BCPR = BN / 8;           // 8, 16

    float acc[FM][FN][4];
#pragma unroll
    for (int i = 0; i < FM; i++)
#pragma unroll
        for (int j = 0; j < FN; j++)
#pragma unroll
            for (int k = 0; k < 4; k++) acc[i][j][k] = 0.f;

    auto load_tiles = [&](int kt, int buf) {
#pragma unroll
        for (int c0 = 0; c0 < ACH; c0 += 256) {
            int c = c0 + tid;
            int r = c / ACPR, co = (c % ACPR) * 8;
            cp_async16(smem_u32(As + buf * ASTG + r * LDA + co),
                       A + (size_t)(bm0 + r) * NN + (size_t)kt * BK + co);
        }
#pragma unroll
        for (int c0 = 0; c0 < BCH; c0 += 256) {
            int c = c0 + tid;
            int r = c / BCPR, co = (c % BCPR) * 8;
            cp_async16(smem_u32(Bs + buf * BSTG + r * LDB + co),
                       B + (size_t)(kt * BK + r) * CC + bn0 + co);
        }
    };

    const int KTL = NN / BK;   // 64
    load_tiles(0, 0);
    cp_commit();
    load_tiles(1, 1);
    cp_commit();

    for (int it = 0; it < KTL; ++it) {
        int buf = it % 3;
        cp_wait1();            // tile `it` resident; `it+1` may still be in flight
        __syncthreads();
        if (it + 2 < KTL) {
            load_tiles(it + 2, (it + 2) % 3);
            cp_commit();
        }
#pragma unroll
        for (int kk = 0; kk < BK / 16; ++kk) {
            uint32_t af[FM][4], bfr[FN][2];
#pragma unroll
            for (int i = 0; i < FM; i++) {
                int r = wm * WARP_M + i * 16 + (lane & 15);
                int cc = kk * 16 + ((lane >> 4) << 3);
                ldsm_x4(af[i], smem_u32(As + buf * ASTG + r * LDA + cc));
            }
#pragma unroll
            for (int j = 0; j < FN; j++) {
                int r = kk * 16 + (lane & 15);
                int cc = wn * WARP_N + j * 8;
                ldsm_x2t(bfr[j], smem_u32(Bs + buf * BSTG + r * LDB + cc));
            }
#pragma unroll
            for (int i = 0; i < FM; i++)
#pragma unroll
                for (int j = 0; j < FN; j++) mma_bf16(acc[i][j], af[i], bfr[j]);
        }
    }

    // epilogue: out = (1-dt)*tgt + dt/(0.25*d[m]) * acc
    const float dt1 = dtp[0];
    const float mdt = 1.f - dt1;
#pragma unroll
    for (int i = 0; i < FM; i++) {
        int rbase = bm0 + wm * WARP_M + i * 16 + (lane >> 2);
#pragma unroll
        for (int h = 0; h < 2; h++) {
            int r = rbase + h * 8;
            float rs = dt1 / (0.25f * dvec[r]);
#pragma unroll
            for (int j = 0; j < FN; j++) {
                int c = bn0 + wn * WARP_N + j * 8 + (lane & 3) * 2;
                size_t idx = (size_t)r * CC + c;
                float2 tg = *reinterpret_cast<const float2*>(tgt + idx);
                float2 o;
                o.x = mdt * tg.x + rs * acc[i][j][h * 2 + 0];
                o.y = mdt * tg.y + rs * acc[i][j][h * 2 + 1];
                *reinterpret_cast<float2*>(outf + idx) = o;
            }
        }
    }
}

// ---------------- host -------------------------------------------------------
extern "C" void kernel_launch(void* const* d_in, const int* in_sizes, int n_in,
                              void* d_out, int out_size) {
    const float* x      = (const float*)d_in[0];
    const float* adj    = (const float*)d_in[1];
    const float* W_proj = (const float*)d_in[2];
    const float* b_proj = (const float*)d_in[3];
    const float* W_pi1  = (const float*)d_in[4];
    const float* b_pi1  = (const float*)d_in[5];
    const float* W_pi2  = (const float*)d_in[6];
    const float* b_pi2  = (const float*)d_in[7];
    const float* W_f    = (const float*)d_in[8];
    const float* b_f    = (const float*)d_in[9];
    const float* dt     = (const float*)d_in[10];
    float* out = (float*)d_out;
    (void)in_sizes; (void)n_in; (void)out_size;

    void *p_adjb, *p_xhi, *p_xlo, *p_wfhi, *p_wflo, *p_wprojb, *p_wpi1b;
    void *p_zb, *p_hb, *p_stb, *p_tgt, *p_q, *p_v, *p_d;
    cudaGetSymbolAddress(&p_adjb, g_adjb);
    cudaGetSymbolAddress(&p_xhi, g_Xhi);
    cudaGetSymbolAddress(&p_xlo, g_Xlo);
    cudaGetSymbolAddress(&p_wfhi, g_Wfhi);
    cudaGetSymbolAddress(&p_wflo, g_Wflo);
    cudaGetSymbolAddress(&p_wprojb, g_Wprojb);
    cudaGetSymbolAddress(&p_wpi1b, g_Wpi1b);
    cudaGetSymbolAddress(&p_zb, g_Zb);
    cudaGetSymbolAddress(&p_hb, g_Hb);
    cudaGetSymbolAddress(&p_stb, g_stb);
    cudaGetSymbolAddress(&p_tgt, g_target);
    cudaGetSymbolAddress(&p_q, g_q);
    cudaGetSymbolAddress(&p_v, g_v);
    cudaGetSymbolAddress(&p_d, g_d);

    bf16* adjb = (bf16*)p_adjb;
    bf16 *Xhi = (bf16*)p_xhi, *Xlo = (bf16*)p_xlo;
    bf16 *Wfhi = (bf16*)p_wfhi, *Wflo = (bf16*)p_wflo;
    bf16 *Wprojb = (bf16*)p_wprojb, *Wpi1b = (bf16*)p_wpi1b;
    bf16 *Zb = (bf16*)p_zb, *Hb = (bf16*)p_hb, *stb = (bf16*)p_stb;
    float *tgt = (float*)p_tgt, *q = (float*)p_q, *v = (float*)p_v, *d = (float*)p_d;

    // dynamic smem opt-in (idempotent)
    const int SM3 = (2 * (128 * 40) * 2 + 2 * (32 * 136) * 2) * 2;  // 75,776 B
    const int SMF = 3 * (128 * 72 + 64 * 136) * 2;                   // 107,520 B
    cudaFuncSetAttribute(gemm_split3, cudaFuncAttributeMaxDynamicSharedMemorySize, SM3);
    cudaFuncSetAttribute(k_final, cudaFuncAttributeMaxDynamicSharedMemorySize, SMF);

    // 1. fused pre: rowsum+convert adj, split x/W_f, convert W_proj/W_pi1
    {
        const int conv_tot = NN * CC + CC * CC + CC * LL + LL * CC;
        const int conv_blocks = (conv_tot + 255) / 256;
        k_pre<<<NN + conv_blocks, 256>>>(adj, adjb, q, x, W_f, W_proj, W_pi1,
                                         Xhi, Xlo, Wfhi, Wflo, Wprojb, Wpi1b);
    }

    // 2. Z = x @ W_proj + b_proj        [4096,64]
    gemm_bf16<128, 64, 32, 4, 2, 0><<<dim3(NN / 128, 1), 256>>>(
        Xhi, Wprojb, NN, LL, CC, b_proj, Zb);

    // 3. H = relu(Z @ W_pi1 + b_pi1)    [4096,512]
    gemm_bf16<128, 128, 32, 2, 4, 1><<<dim3(NN / 128, CC / 128), 256>>>(
        Zb, Wpi1b, NN, CC, LL, b_pi1, Hb);

    // 4. pi, v = pi/q
    k_pi<<<NN, 128>>>(Hb, W_pi2, b_pi2, q, v);

    // 5. d = adjb @ v + 1e-5
    k_dvec<<<NN, 256>>>(adjb, v, d);

    // 6. target = relu(x @ W_f + b_f) fp32-accurate; stb = v[r]*target (bf16)
    gemm_split3<<<dim3(NN / 128, CC / 128), 256, SM3>>>(
        Xhi, Xlo, Wfhi, Wflo, b_f, v, tgt, stb);

    // 7. out = (1-dt)*target + (dt/(eps*d[m])) * (adjb @ stb)
    k_final<<<dim3(NN / 128, CC / 128), 256, SMF>>>(adjb, stb, d, tgt, dt, out);
}